// round 10
// baseline (speedup 1.0000x reference)
#include <cuda_runtime.h>

// LorenzPINN: per-row forward + JVP of a 1->20->20->20->20->3 tanh MLP + Lorenz
// residuals. fp32, transposed f32x2 accumulation (R6 layout, 4B/weight smem).
// R8: tanh reverted to EX2/RCP (MUFU.TANH is slow on sm_103a — R7 regression).
//     Occupancy push: launch_bounds(192,4) -> 24 warps/SM (reg cap 85), made
//     feasible by a fully-packed f32x2 epilogue (state kept as u64 pairs,
//     mul2/add2/fma2 on (z0,z1) pairs, sign-flip trick for the derivative).

#define W  20
#define JP 10          // j-pairs per layer
typedef unsigned long long u64;

__device__ __forceinline__ u64 pack2(float lo, float hi) {
    u64 r; asm("mov.b64 %0,{%1,%2};" : "=l"(r) : "f"(lo), "f"(hi)); return r;
}
__device__ __forceinline__ u64 dup2(float x) {
    u64 r; asm("mov.b64 %0,{%1,%1};" : "=l"(r) : "f"(x)); return r;
}
__device__ __forceinline__ void unpack2(u64 v, float& lo, float& hi) {
    asm("mov.b64 {%0,%1},%2;" : "=f"(lo), "=f"(hi) : "l"(v));
}
__device__ __forceinline__ float lo2(u64 v) {
    float a, b; unpack2(v, a, b); return a;
}
__device__ __forceinline__ float hi2(u64 v) {
    float a, b; unpack2(v, a, b); return b;
}
__device__ __forceinline__ u64 ffma2(u64 a, u64 b, u64 c) {
    u64 d; asm("fma.rn.f32x2 %0,%1,%2,%3;" : "=l"(d) : "l"(a), "l"(b), "l"(c)); return d;
}
__device__ __forceinline__ u64 fmul2(u64 a, u64 b) {
    u64 d; asm("mul.rn.f32x2 %0,%1,%2;" : "=l"(d) : "l"(a), "l"(b)); return d;
}
__device__ __forceinline__ u64 fadd2(u64 a, u64 b) {
    u64 d; asm("add.rn.f32x2 %0,%1,%2;" : "=l"(d) : "l"(a), "l"(b)); return d;
}

__device__ __forceinline__ float mufu_ex2(float x) {
    float e; asm("ex2.approx.f32 %0, %1;" : "=f"(e) : "f"(x)); return e;
}
__device__ __forceinline__ float mufu_rcp(float x) {
    float r; asm("rcp.approx.f32 %0, %1;" : "=f"(r) : "f"(x)); return r;
}

#define C2LOG2E 2.885390081777927f   // 2*log2(e)
#define SGNMASK 0x8000000080000000ULL

// scalar tanh for layer 1: 1 - 2/(e^{2x}+1)
__device__ __forceinline__ float fast_tanh(float x) {
    return fmaf(-2.0f, mufu_rcp(mufu_ex2(x * C2LOG2E) + 1.0f), 1.0f);
}

// One hidden layer, transposed, fully packed state (th2/td2 = (v_2jj, v_2jj+1)).
// sw[k*JP+jj] = (W[k][2jj], W[k][2jj+1]); sbp[jj] = (b[2jj], b[2jj+1]).
__device__ __forceinline__ void layerT(u64 (&th2)[JP], u64 (&td2)[JP],
                                       const u64* __restrict__ sw,
                                       const u64* __restrict__ sbp,
                                       u64 Cc, u64 One2, u64 M2) {
    u64 av[JP], ad[JP];
#pragma unroll
    for (int jj = 0; jj < JP; jj++) { av[jj] = sbp[jj]; ad[jj] = 0ULL; }
#pragma unroll
    for (int k = 0; k < W; k++) {
        float hs = (k & 1) ? hi2(th2[k >> 1]) : lo2(th2[k >> 1]);  // free reg pick
        float ds = (k & 1) ? hi2(td2[k >> 1]) : lo2(td2[k >> 1]);
        u64 hk = dup2(hs);
        u64 dk = dup2(ds);
        const ulonglong2* rowk = reinterpret_cast<const ulonglong2*>(sw + k * JP);
#pragma unroll
        for (int q = 0; q < JP / 2; q++) {
            ulonglong2 wp = rowk[q];        // one LDS.128 feeds 4 FFMA2
            av[2 * q + 0] = ffma2(hk, wp.x, av[2 * q + 0]);
            ad[2 * q + 0] = ffma2(dk, wp.x, ad[2 * q + 0]);
            av[2 * q + 1] = ffma2(hk, wp.y, av[2 * q + 1]);
            ad[2 * q + 1] = ffma2(dk, wp.y, ad[2 * q + 1]);
        }
    }
    // Packed epilogue: t = 1 - 2*rcp(ex2(c*z)+1); td = dp - t^2*dp.
#pragma unroll
    for (int jj = 0; jj < JP; jj++) {
        u64 zc = fmul2(av[jj], Cc);                         // (c*z0, c*z1)
        u64 e  = pack2(mufu_ex2(lo2(zc)), mufu_ex2(hi2(zc)));
        u64 ep = fadd2(e, One2);
        u64 r  = pack2(mufu_rcp(lo2(ep)), mufu_rcp(hi2(ep)));
        u64 tt = ffma2(M2, r, One2);                        // (t0, t1)
        th2[jj] = tt;
        u64 tn = tt ^ SGNMASK;                              // (-t0, -t1), ALU
        u64 s  = fmul2(tn, ad[jj]);                         // -t*dp
        td2[jj] = ffma2(tt, s, ad[jj]);                     // dp - t^2*dp
    }
}

__global__ __launch_bounds__(192, 4)
void lorenz_pinn_kernel(const float* __restrict__ t,
                        const float* __restrict__ W1, const float* __restrict__ b1,
                        const float* __restrict__ W2, const float* __restrict__ b2,
                        const float* __restrict__ W3, const float* __restrict__ b3,
                        const float* __restrict__ W4, const float* __restrict__ b4,
                        const float* __restrict__ Wo, const float* __restrict__ bo,
                        const float* __restrict__ c1p, const float* __restrict__ c2p,
                        const float* __restrict__ c3p,
                        float* __restrict__ out, int n) {
    __shared__ __align__(16) u64 sW2[W * JP];
    __shared__ __align__(16) u64 sW3[W * JP];
    __shared__ __align__(16) u64 sW4[W * JP];
    __shared__ __align__(16) u64 sWoD[3 * W];   // dup'd (w,w) head weights
    __shared__ u64 sb2p[JP], sb3p[JP], sb4p[JP];
    __shared__ float sW1[W], sb1[W], sbo[4];

    for (int idx = threadIdx.x; idx < W * JP; idx += blockDim.x) {
        int k = idx / JP, jj = idx % JP;
        int j0 = 2 * jj, j1 = 2 * jj + 1;
        sW2[idx] = pack2(W2[k * W + j0], W2[k * W + j1]);
        sW3[idx] = pack2(W3[k * W + j0], W3[k * W + j1]);
        sW4[idx] = pack2(W4[k * W + j0], W4[k * W + j1]);
    }
    if (threadIdx.x < 3 * W) {
        int c = threadIdx.x / W, k = threadIdx.x % W;
        float w = Wo[k * 3 + c];
        sWoD[c * W + k] = pack2(w, w);
    }
    if (threadIdx.x < JP) {
        int jj = threadIdx.x;
        sb2p[jj] = pack2(b2[2 * jj], b2[2 * jj + 1]);
        sb3p[jj] = pack2(b3[2 * jj], b3[2 * jj + 1]);
        sb4p[jj] = pack2(b4[2 * jj], b4[2 * jj + 1]);
    }
    if (threadIdx.x < W) {
        sW1[threadIdx.x] = W1[threadIdx.x];
        sb1[threadIdx.x] = b1[threadIdx.x];
    }
    if (threadIdx.x < 3) sbo[threadIdx.x] = bo[threadIdx.x];
    __syncthreads();

    int i = blockIdx.x * blockDim.x + threadIdx.x;
    if (i >= n) return;

    float tv = t[i];
    float C1 = __ldg(c1p), C2 = __ldg(c2p), C3 = __ldg(c3p);

    u64 Cc   = dup2(C2LOG2E);
    u64 One2 = dup2(1.0f);
    u64 M2   = dup2(-2.0f);

    // Layer 1: pre = t*W1 + b1, dpre = W1 (tangent of t is 1). Packed state.
    u64 th2[JP], td2[JP];
#pragma unroll
    for (int jj = 0; jj < JP; jj++) {
        float w0 = sW1[2 * jj], w1 = sW1[2 * jj + 1];
        float t0 = fast_tanh(fmaf(tv, w0, sb1[2 * jj]));
        float t1 = fast_tanh(fmaf(tv, w1, sb1[2 * jj + 1]));
        th2[jj] = pack2(t0, t1);
        td2[jj] = pack2(fmaf(-t0, t0 * w0, w0), fmaf(-t1, t1 * w1, w1));
    }

    layerT(th2, td2, sW2, sb2p, Cc, One2, M2);
    layerT(th2, td2, sW3, sb3p, Cc, One2, M2);
    layerT(th2, td2, sW4, sb4p, Cc, One2, M2);

    // Output head: pack (value, tangent) per k; dup'd weights -> acc = (o_c, d_c).
    float o[3], d[3];
#pragma unroll
    for (int c = 0; c < 3; c++) {
        u64 acc = pack2(sbo[c], 0.0f);
        const ulonglong2* row = reinterpret_cast<const ulonglong2*>(sWoD + c * W);
#pragma unroll
        for (int q = 0; q < W / 2; q++) {
            ulonglong2 wp = row[q];
            int kk0 = 2 * q, kk1 = 2 * q + 1;  // units 2q*? -> k = 2q,2q+1
            u64 hd0 = pack2(lo2(th2[q]), lo2(td2[q]));       // k = 2q
            u64 hd1 = pack2(hi2(th2[q]), hi2(td2[q]));       // k = 2q+1
            (void)kk0; (void)kk1;
            acc = ffma2(hd0, wp.x, acc);
            acc = ffma2(hd1, wp.y, acc);
        }
        unpack2(acc, o[c], d[c]);
    }

    float x = o[0], y = o[1], z = o[2];
    float fx = d[0] - C1 * (y - x);
    float fy = d[1] - x * (C2 - z) + y;
    float fz = d[2] - x * y + C3 * z;

    float2* po = reinterpret_cast<float2*>(out + (size_t)i * 6);
    po[0] = make_float2(x, y);
    po[1] = make_float2(z, fx);
    po[2] = make_float2(fy, fz);
}

extern "C" void kernel_launch(void* const* d_in, const int* in_sizes, int n_in,
                              void* d_out, int out_size) {
    const float* t  = (const float*)d_in[0];
    const float* W1 = (const float*)d_in[1];
    const float* b1 = (const float*)d_in[2];
    const float* W2 = (const float*)d_in[3];
    const float* b2 = (const float*)d_in[4];
    const float* W3 = (const float*)d_in[5];
    const float* b3 = (const float*)d_in[6];
    const float* W4 = (const float*)d_in[7];
    const float* b4 = (const float*)d_in[8];
    const float* Wo = (const float*)d_in[9];
    const float* bo = (const float*)d_in[10];
    const float* c1 = (const float*)d_in[11];
    const float* c2 = (const float*)d_in[12];
    const float* c3 = (const float*)d_in[13];
    float* out = (float*)d_out;
    int n = in_sizes[0];
    int blocks = (n + 191) / 192;
    lorenz_pinn_kernel<<<blocks, 192>>>(t, W1, b1, W2, b2, W3, b3, W4, b4,
                                        Wo, bo, c1, c2, c3, out, n);
}

// round 11
// speedup vs baseline: 1.3778x; 1.3778x over previous
#include <cuda_runtime.h>

// LorenzPINN: per-row forward + JVP of a 1->20->20->20->20->3 tanh MLP + Lorenz
// residuals. fp32, transposed f32x2 accumulation (R6 compute structure).
// R9: weights moved from shared memory to __constant__ (pack kernel -> one
//     cudaMemcpyToSymbolAsync -> main kernel). Weight fetches become uniform
//     constant loads (ULDC/LDCU, separate port) instead of LDS broadcasts,
//     freeing the LSU crossbar (74us busy in R6) and leaving fma as the only
//     binder. R8 lesson applied: no reg cap below natural fit (96).

#define W  20
#define JP 10
typedef unsigned long long u64;

struct __align__(16) CW {
    u64 w2[W * JP];     // (W2[k][2jj], W2[k][2jj+1]) == raw row-major as u64
    u64 w3[W * JP];
    u64 w4[W * JP];
    u64 wo[3 * W];      // dup'd (w,w), wo[c*W+k] = (Wo[k][c], Wo[k][c])
    u64 b2[JP], b3[JP], b4[JP];   // (b[2jj], b[2jj+1]) == raw as u64
    float w1[W], b1[W], bo[3];
    float c1, c2, c3;
};
__constant__ CW cw;
__device__ CW gstage;

__device__ __forceinline__ u64 pack2(float lo, float hi) {
    u64 r; asm("mov.b64 %0,{%1,%2};" : "=l"(r) : "f"(lo), "f"(hi)); return r;
}
__device__ __forceinline__ u64 dup2(float x) {
    u64 r; asm("mov.b64 %0,{%1,%1};" : "=l"(r) : "f"(x)); return r;
}
__device__ __forceinline__ void unpack2(u64 v, float& lo, float& hi) {
    asm("mov.b64 {%0,%1},%2;" : "=f"(lo), "=f"(hi) : "l"(v));
}
__device__ __forceinline__ u64 ffma2(u64 a, u64 b, u64 c) {
    u64 d; asm("fma.rn.f32x2 %0,%1,%2,%3;" : "=l"(d) : "l"(a), "l"(b), "l"(c)); return d;
}

#define C2LOG2E 2.885390081777927f   // 2*log2(e)

// tanh(x) = 1 - 2/(e^{2x}+1) via MUFU EX2 + RCP. Saturates correctly at +-inf.
__device__ __forceinline__ float fast_tanh(float x) {
    float e;
    asm("ex2.approx.f32 %0, %1;" : "=f"(e) : "f"(x * C2LOG2E));
    float r;
    asm("rcp.approx.f32 %0, %1;" : "=f"(r) : "f"(e + 1.0f));
    return fmaf(-2.0f, r, 1.0f);
}

// ---- pack kernel: gather weights from d_in buffers into the staging struct ----
__global__ void pack_kernel(const float* __restrict__ W1, const float* __restrict__ b1,
                            const float* __restrict__ W2, const float* __restrict__ b2,
                            const float* __restrict__ W3, const float* __restrict__ b3,
                            const float* __restrict__ W4, const float* __restrict__ b4,
                            const float* __restrict__ Wo, const float* __restrict__ bo,
                            const float* __restrict__ c1, const float* __restrict__ c2,
                            const float* __restrict__ c3) {
    int t = threadIdx.x;
    const u64* pw2 = (const u64*)W2;   // adjacent-j pairs are raw u64s (8B-aligned)
    const u64* pw3 = (const u64*)W3;
    const u64* pw4 = (const u64*)W4;
    for (int i = t; i < W * JP; i += blockDim.x) {
        gstage.w2[i] = pw2[i];
        gstage.w3[i] = pw3[i];
        gstage.w4[i] = pw4[i];
    }
    if (t < 3 * W) {
        int c = t / W, k = t % W;
        float w = Wo[k * 3 + c];
        gstage.wo[c * W + k] = pack2(w, w);
    }
    if (t < JP) {
        gstage.b2[t] = ((const u64*)b2)[t];
        gstage.b3[t] = ((const u64*)b3)[t];
        gstage.b4[t] = ((const u64*)b4)[t];
    }
    if (t < W) {
        gstage.w1[t] = W1[t];
        gstage.b1[t] = b1[t];
    }
    if (t < 3) gstage.bo[t] = bo[t];
    if (t == 0) { gstage.c1 = *c1; gstage.c2 = *c2; gstage.c3 = *c3; }
}

// One hidden layer, transposed, weights from __constant__ (direct indexing so
// the compiler keeps const-space loads with immediate offsets -> ULDC).
#define LAYERC(SW, SB)                                                        \
    do {                                                                      \
        u64 av[JP], ad[JP];                                                   \
        _Pragma("unroll")                                                     \
        for (int jj = 0; jj < JP; jj++) { av[jj] = cw.SB[jj]; ad[jj] = 0ULL; }\
        _Pragma("unroll")                                                     \
        for (int k = 0; k < W; k++) {                                         \
            u64 hk = dup2(th[k]);                                             \
            u64 dk = dup2(td[k]);                                             \
            _Pragma("unroll")                                                 \
            for (int jj = 0; jj < JP; jj++) {                                 \
                u64 wp = cw.SW[k * JP + jj];                                  \
                av[jj] = ffma2(hk, wp, av[jj]);                               \
                ad[jj] = ffma2(dk, wp, ad[jj]);                               \
            }                                                                 \
        }                                                                     \
        _Pragma("unroll")                                                     \
        for (int jj = 0; jj < JP; jj++) {                                     \
            float z0, z1, dp0, dp1;                                           \
            unpack2(av[jj], z0, z1);                                          \
            unpack2(ad[jj], dp0, dp1);                                        \
            float t0 = fast_tanh(z0);                                         \
            float t1 = fast_tanh(z1);                                         \
            th[2 * jj + 0] = t0;                                              \
            th[2 * jj + 1] = t1;                                              \
            td[2 * jj + 0] = fmaf(-t0, t0 * dp0, dp0);                        \
            td[2 * jj + 1] = fmaf(-t1, t1 * dp1, dp1);                        \
        }                                                                     \
    } while (0)

__global__ __launch_bounds__(192, 3)
void lorenz_pinn_kernel(const float* __restrict__ t,
                        float* __restrict__ out, int n) {
    int i = blockIdx.x * blockDim.x + threadIdx.x;
    if (i >= n) return;

    float tv = t[i];
    float C1 = cw.c1, C2 = cw.c2, C3 = cw.c3;

    // Layer 1: pre = t*W1 + b1, dpre = W1 (tangent of t is 1). Scalar state.
    float th[W], td[W];
#pragma unroll
    for (int j = 0; j < W; j++) {
        float w = cw.w1[j];
        float t0 = fast_tanh(fmaf(tv, w, cw.b1[j]));
        th[j] = t0;
        td[j] = fmaf(-t0, t0 * w, w);
    }

    LAYERC(w2, b2);
    LAYERC(w3, b3);
    LAYERC(w4, b4);

    // Output head: pack (value, tangent) per k; dup'd weights -> acc = (o_c, d_c).
    u64 hd[W];
#pragma unroll
    for (int k = 0; k < W; k++) hd[k] = pack2(th[k], td[k]);

    float o[3], d[3];
#pragma unroll
    for (int c = 0; c < 3; c++) {
        u64 acc = pack2(cw.bo[c], 0.0f);
#pragma unroll
        for (int k = 0; k < W; k++)
            acc = ffma2(hd[k], cw.wo[c * W + k], acc);
        unpack2(acc, o[c], d[c]);
    }

    float x = o[0], y = o[1], z = o[2];
    float fx = d[0] - C1 * (y - x);
    float fy = d[1] - x * (C2 - z) + y;
    float fz = d[2] - x * y + C3 * z;

    float2* po = reinterpret_cast<float2*>(out + (size_t)i * 6);
    po[0] = make_float2(x, y);
    po[1] = make_float2(z, fx);
    po[2] = make_float2(fy, fz);
}

extern "C" void kernel_launch(void* const* d_in, const int* in_sizes, int n_in,
                              void* d_out, int out_size) {
    const float* t  = (const float*)d_in[0];
    const float* W1 = (const float*)d_in[1];
    const float* b1 = (const float*)d_in[2];
    const float* W2 = (const float*)d_in[3];
    const float* b2 = (const float*)d_in[4];
    const float* W3 = (const float*)d_in[5];
    const float* b3 = (const float*)d_in[6];
    const float* W4 = (const float*)d_in[7];
    const float* b4 = (const float*)d_in[8];
    const float* Wo = (const float*)d_in[9];
    const float* bo = (const float*)d_in[10];
    const float* c1 = (const float*)d_in[11];
    const float* c2 = (const float*)d_in[12];
    const float* c3 = (const float*)d_in[13];
    float* out = (float*)d_out;
    int n = in_sizes[0];

    // 1) Gather+pack weights into the device staging struct.
    pack_kernel<<<1, 256>>>(W1, b1, W2, b2, W3, b3, W4, b4, Wo, bo, c1, c2, c3);

    // 2) One D2D copy staging -> __constant__ (graph-capturable memcpy node).
    void* src = nullptr;
    cudaGetSymbolAddress(&src, gstage);
    cudaMemcpyToSymbolAsync(cw, src, sizeof(CW), 0, cudaMemcpyDeviceToDevice, 0);

    // 3) Main kernel.
    int blocks = (n + 191) / 192;
    lorenz_pinn_kernel<<<blocks, 192>>>(t, out, n);
}

// round 12
// speedup vs baseline: 1.4015x; 1.0172x over previous
#include <cuda_runtime.h>

// LorenzPINN: per-row forward + JVP of a 1->20->20->20->20->3 tanh MLP + Lorenz
// residuals. fp32, transposed f32x2 accumulation, weights in __constant__
// (R9: pack kernel -> cudaMemcpyToSymbolAsync -> main kernel; L1 traffic ~0).
// R10: occupancy via block shape — block=64, launch_bounds(64,11) -> 22
//      warps/SM at natural 88 regs (R9 was 18 warps; fma pipe at 69% with
//      ~36us latency exposure). No reg cap below natural fit (R8 lesson).

#define W  20
#define JP 10
typedef unsigned long long u64;

struct __align__(16) CW {
    u64 w2[W * JP];     // (W2[k][2jj], W2[k][2jj+1]) == raw row-major as u64
    u64 w3[W * JP];
    u64 w4[W * JP];
    u64 wo[3 * W];      // dup'd (w,w), wo[c*W+k] = (Wo[k][c], Wo[k][c])
    u64 b2[JP], b3[JP], b4[JP];   // (b[2jj], b[2jj+1]) == raw as u64
    float w1[W], b1[W], bo[3];
    float c1, c2, c3;
};
__constant__ CW cw;
__device__ CW gstage;

__device__ __forceinline__ u64 pack2(float lo, float hi) {
    u64 r; asm("mov.b64 %0,{%1,%2};" : "=l"(r) : "f"(lo), "f"(hi)); return r;
}
__device__ __forceinline__ u64 dup2(float x) {
    u64 r; asm("mov.b64 %0,{%1,%1};" : "=l"(r) : "f"(x)); return r;
}
__device__ __forceinline__ void unpack2(u64 v, float& lo, float& hi) {
    asm("mov.b64 {%0,%1},%2;" : "=f"(lo), "=f"(hi) : "l"(v));
}
__device__ __forceinline__ u64 ffma2(u64 a, u64 b, u64 c) {
    u64 d; asm("fma.rn.f32x2 %0,%1,%2,%3;" : "=l"(d) : "l"(a), "l"(b), "l"(c)); return d;
}

#define C2LOG2E 2.885390081777927f   // 2*log2(e)

// tanh(x) = 1 - 2/(e^{2x}+1) via MUFU EX2 + RCP. Saturates correctly at +-inf.
__device__ __forceinline__ float fast_tanh(float x) {
    float e;
    asm("ex2.approx.f32 %0, %1;" : "=f"(e) : "f"(x * C2LOG2E));
    float r;
    asm("rcp.approx.f32 %0, %1;" : "=f"(r) : "f"(e + 1.0f));
    return fmaf(-2.0f, r, 1.0f);
}

// ---- pack kernel: gather weights from d_in buffers into the staging struct ----
__global__ void pack_kernel(const float* __restrict__ W1, const float* __restrict__ b1,
                            const float* __restrict__ W2, const float* __restrict__ b2,
                            const float* __restrict__ W3, const float* __restrict__ b3,
                            const float* __restrict__ W4, const float* __restrict__ b4,
                            const float* __restrict__ Wo, const float* __restrict__ bo,
                            const float* __restrict__ c1, const float* __restrict__ c2,
                            const float* __restrict__ c3) {
    int t = threadIdx.x;
    const u64* pw2 = (const u64*)W2;   // adjacent-j pairs are raw u64s (8B-aligned)
    const u64* pw3 = (const u64*)W3;
    const u64* pw4 = (const u64*)W4;
    for (int i = t; i < W * JP; i += blockDim.x) {
        gstage.w2[i] = pw2[i];
        gstage.w3[i] = pw3[i];
        gstage.w4[i] = pw4[i];
    }
    if (t < 3 * W) {
        int c = t / W, k = t % W;
        float w = Wo[k * 3 + c];
        gstage.wo[c * W + k] = pack2(w, w);
    }
    if (t < JP) {
        gstage.b2[t] = ((const u64*)b2)[t];
        gstage.b3[t] = ((const u64*)b3)[t];
        gstage.b4[t] = ((const u64*)b4)[t];
    }
    if (t < W) {
        gstage.w1[t] = W1[t];
        gstage.b1[t] = b1[t];
    }
    if (t < 3) gstage.bo[t] = bo[t];
    if (t == 0) { gstage.c1 = *c1; gstage.c2 = *c2; gstage.c3 = *c3; }
}

// One hidden layer, transposed, weights from __constant__ with immediate
// offsets (uniform constant-port loads, no LSU traffic).
#define LAYERC(SW, SB)                                                        \
    do {                                                                      \
        u64 av[JP], ad[JP];                                                   \
        _Pragma("unroll")                                                     \
        for (int jj = 0; jj < JP; jj++) { av[jj] = cw.SB[jj]; ad[jj] = 0ULL; }\
        _Pragma("unroll")                                                     \
        for (int k = 0; k < W; k++) {                                         \
            u64 hk = dup2(th[k]);                                             \
            u64 dk = dup2(td[k]);                                             \
            _Pragma("unroll")                                                 \
            for (int jj = 0; jj < JP; jj++) {                                 \
                u64 wp = cw.SW[k * JP + jj];                                  \
                av[jj] = ffma2(hk, wp, av[jj]);                               \
                ad[jj] = ffma2(dk, wp, ad[jj]);                               \
            }                                                                 \
        }                                                                     \
        _Pragma("unroll")                                                     \
        for (int jj = 0; jj < JP; jj++) {                                     \
            float z0, z1, dp0, dp1;                                           \
            unpack2(av[jj], z0, z1);                                          \
            unpack2(ad[jj], dp0, dp1);                                        \
            float t0 = fast_tanh(z0);                                         \
            float t1 = fast_tanh(z1);                                         \
            th[2 * jj + 0] = t0;                                              \
            th[2 * jj + 1] = t1;                                              \
            td[2 * jj + 0] = fmaf(-t0, t0 * dp0, dp0);                        \
            td[2 * jj + 1] = fmaf(-t1, t1 * dp1, dp1);                        \
        }                                                                     \
    } while (0)

__global__ __launch_bounds__(64, 11)
void lorenz_pinn_kernel(const float* __restrict__ t,
                        float* __restrict__ out, int n) {
    int i = blockIdx.x * blockDim.x + threadIdx.x;
    if (i >= n) return;

    float tv = __ldg(t + i);
    float C1 = cw.c1, C2 = cw.c2, C3 = cw.c3;

    // Layer 1: pre = t*W1 + b1, dpre = W1 (tangent of t is 1). Scalar state.
    float th[W], td[W];
#pragma unroll
    for (int j = 0; j < W; j++) {
        float w = cw.w1[j];
        float t0 = fast_tanh(fmaf(tv, w, cw.b1[j]));
        th[j] = t0;
        td[j] = fmaf(-t0, t0 * w, w);
    }

    LAYERC(w2, b2);
    LAYERC(w3, b3);
    LAYERC(w4, b4);

    // Output head: pack (value, tangent) per k; dup'd weights -> acc = (o_c, d_c).
    u64 hd[W];
#pragma unroll
    for (int k = 0; k < W; k++) hd[k] = pack2(th[k], td[k]);

    float o[3], d[3];
#pragma unroll
    for (int c = 0; c < 3; c++) {
        u64 acc = pack2(cw.bo[c], 0.0f);
#pragma unroll
        for (int k = 0; k < W; k++)
            acc = ffma2(hd[k], cw.wo[c * W + k], acc);
        unpack2(acc, o[c], d[c]);
    }

    float x = o[0], y = o[1], z = o[2];
    float fx = d[0] - C1 * (y - x);
    float fy = d[1] - x * (C2 - z) + y;
    float fz = d[2] - x * y + C3 * z;

    float2* po = reinterpret_cast<float2*>(out + (size_t)i * 6);
    po[0] = make_float2(x, y);
    po[1] = make_float2(z, fx);
    po[2] = make_float2(fy, fz);
}

extern "C" void kernel_launch(void* const* d_in, const int* in_sizes, int n_in,
                              void* d_out, int out_size) {
    const float* t  = (const float*)d_in[0];
    const float* W1 = (const float*)d_in[1];
    const float* b1 = (const float*)d_in[2];
    const float* W2 = (const float*)d_in[3];
    const float* b2 = (const float*)d_in[4];
    const float* W3 = (const float*)d_in[5];
    const float* b3 = (const float*)d_in[6];
    const float* W4 = (const float*)d_in[7];
    const float* b4 = (const float*)d_in[8];
    const float* Wo = (const float*)d_in[9];
    const float* bo = (const float*)d_in[10];
    const float* c1 = (const float*)d_in[11];
    const float* c2 = (const float*)d_in[12];
    const float* c3 = (const float*)d_in[13];
    float* out = (float*)d_out;
    int n = in_sizes[0];

    // 1) Gather+pack weights into the device staging struct.
    pack_kernel<<<1, 256>>>(W1, b1, W2, b2, W3, b3, W4, b4, Wo, bo, c1, c2, c3);

    // 2) One D2D copy staging -> __constant__ (graph-capturable memcpy node).
    void* src = nullptr;
    cudaGetSymbolAddress(&src, gstage);
    cudaMemcpyToSymbolAsync(cw, src, sizeof(CW), 0, cudaMemcpyDeviceToDevice, 0);

    // 3) Main kernel.
    int blocks = (n + 63) / 64;
    lorenz_pinn_kernel<<<blocks, 64>>>(t, out, n);
}